// round 8
// baseline (speedup 1.0000x reference)
#include <cuda_runtime.h>
#include <cuda_bf16.h>
#include <cstdint>

// Problem constants (fixed by the dataset):
//   x: [B=4096, D=2048], weight: [C=32768, D=2048], weight2: [D, D]
//   out: [B, C] float32
#define DDIM 2048
#define BMAX 4096
#define CMAX 32768
#define EPS_NRM 1e-12f

// Scratch (allocation-free rule: __device__ globals). Every element is
// overwritten on every launch -> deterministic across graph replays.
__device__ float g_inv_cn[DDIM];   // 1 / max(||weight2[:,j]||, eps)
__device__ float g_s[DDIM];        // s[d] = sum_j weight2[d,j] * inv_cn[j]
__device__ float g_xs[BMAX];       // xn . s
__device__ float g_ms[CMAX];       // mean . s

// ---------------------------------------------------------------------------
// Reductions
// ---------------------------------------------------------------------------
__device__ __forceinline__ float2 block_reduce2(float a, float b) {
    #pragma unroll
    for (int o = 16; o; o >>= 1) {
        a += __shfl_xor_sync(0xffffffffu, a, o);
        b += __shfl_xor_sync(0xffffffffu, b, o);
    }
    __shared__ float sa[32], sb[32];
    int w = threadIdx.x >> 5, l = threadIdx.x & 31;
    if (l == 0) { sa[w] = a; sb[w] = b; }
    __syncthreads();
    int nw = (blockDim.x + 31) >> 5;
    a = (threadIdx.x < (unsigned)nw) ? sa[threadIdx.x] : 0.0f;
    b = (threadIdx.x < (unsigned)nw) ? sb[threadIdx.x] : 0.0f;
    if (w == 0) {
        #pragma unroll
        for (int o = 16; o; o >>= 1) {
            a += __shfl_xor_sync(0xffffffffu, a, o);
            b += __shfl_xor_sync(0xffffffffu, b, o);
        }
    }
    return make_float2(a, b);  // valid in thread 0
}

__device__ __forceinline__ float block_reduce1(float a) {
    #pragma unroll
    for (int o = 16; o; o >>= 1) a += __shfl_xor_sync(0xffffffffu, a, o);
    __shared__ float sa[32];
    int w = threadIdx.x >> 5, l = threadIdx.x & 31;
    if (l == 0) sa[w] = a;
    __syncthreads();
    int nw = (blockDim.x + 31) >> 5;
    a = (threadIdx.x < (unsigned)nw) ? sa[threadIdx.x] : 0.0f;
    if (w == 0) {
        #pragma unroll
        for (int o = 16; o; o >>= 1) a += __shfl_xor_sync(0xffffffffu, a, o);
    }
    return a;  // valid in thread 0
}

// ---------------------------------------------------------------------------
// 1) inv column norms of weight2: coalesced tile reduction down the rows.
//    block = (32, 8); warp reads 32 consecutive columns of one row (128B line).
// ---------------------------------------------------------------------------
__global__ void k_colnorm(const float* __restrict__ w2) {
    int j = blockIdx.x * 32 + threadIdx.x;
    float acc = 0.0f;
    #pragma unroll 4
    for (int d = threadIdx.y; d < DDIM; d += 8) {
        float v = __ldg(&w2[(size_t)d * DDIM + j]);
        acc = fmaf(v, v, acc);
    }
    __shared__ float sh[8][32];
    sh[threadIdx.y][threadIdx.x] = acc;
    __syncthreads();
    if (threadIdx.y == 0) {
        float t = 0.0f;
        #pragma unroll
        for (int y = 0; y < 8; y++) t += sh[y][threadIdx.x];
        g_inv_cn[j] = 1.0f / fmaxf(sqrtf(t), EPS_NRM);
    }
}

// ---------------------------------------------------------------------------
// 2) s[d] = sum_j weight2[d,j] * inv_cn[j].  One block per row, float4 loads.
// ---------------------------------------------------------------------------
__global__ void k_rowsum_s(const float* __restrict__ w2) {
    int d = blockIdx.x;
    const float4* row = reinterpret_cast<const float4*>(w2 + (size_t)d * DDIM);
    const float4* icn = reinterpret_cast<const float4*>(g_inv_cn);
    float acc = 0.0f;
    #pragma unroll
    for (int j = threadIdx.x; j < DDIM / 4; j += 256) {
        float4 v = __ldg(&row[j]);
        float4 c = icn[j];
        acc += v.x * c.x + v.y * c.y + v.z * c.z + v.w * c.w;
    }
    float t = block_reduce1(acc);
    if (threadIdx.x == 0) g_s[d] = t;
}

// ---------------------------------------------------------------------------
// 3/4) out[r] = (row . s) / max(||row||, eps).  One block per row.
//      Single pass: dot and sum-of-squares fused -> one read of the matrix.
// ---------------------------------------------------------------------------
__global__ void k_norm_dot(const float* __restrict__ mat, float* __restrict__ out) {
    int r = blockIdx.x;
    const float4* row = reinterpret_cast<const float4*>(mat + (size_t)r * DDIM);
    const float4* sv  = reinterpret_cast<const float4*>(g_s);
    float dot = 0.0f, ss = 0.0f;
    #pragma unroll
    for (int j = threadIdx.x; j < DDIM / 4; j += 256) {
        float4 v  = __ldg(&row[j]);
        float4 s4 = sv[j];
        dot += v.x * s4.x + v.y * s4.y + v.z * s4.z + v.w * s4.w;
        ss  += v.x * v.x  + v.y * v.y  + v.z * v.z  + v.w * v.w;
    }
    float2 t = block_reduce2(dot, ss);
    if (threadIdx.x == 0)
        out[r] = t.x / fmaxf(sqrtf(t.y), EPS_NRM);
}

// ---------------------------------------------------------------------------
// 5) out[b,c] = ms[c] - xs[b].  Pure streaming write (512 MB), float4 STG.
//    grid = (C/(4*256*8), B); each thread writes 8 float4 in one row.
// ---------------------------------------------------------------------------
__global__ void k_logit(float* __restrict__ out, int Cdim) {
    int b = blockIdx.y;
    float xsb = g_xs[b];
    const float4* ms4 = reinterpret_cast<const float4*>(g_ms);
    float4* o4 = reinterpret_cast<float4*>(out) + (size_t)b * (Cdim >> 2);
    int base = blockIdx.x * (256 * 8) + threadIdx.x;
    #pragma unroll
    for (int k = 0; k < 8; k++) {
        int c4 = base + k * 256;
        float4 m = ms4[c4];
        o4[c4] = make_float4(m.x - xsb, m.y - xsb, m.z - xsb, m.w - xsb);
    }
}

// ---------------------------------------------------------------------------
extern "C" void kernel_launch(void* const* d_in, const int* in_sizes, int n_in,
                              void* d_out, int out_size) {
    const float* x  = (const float*)d_in[0];   // [B, D]
    const float* w  = (const float*)d_in[1];   // [C, D]
    const float* w2 = (const float*)d_in[2];   // [D, D]
    float* out = (float*)d_out;                // [B, C]

    const int B = in_sizes[0] / DDIM;          // 4096
    const int C = in_sizes[1] / DDIM;          // 32768

    float* p_xs; cudaGetSymbolAddress((void**)&p_xs, g_xs);
    float* p_ms; cudaGetSymbolAddress((void**)&p_ms, g_ms);

    // 1) inv column norms of weight2
    k_colnorm<<<DDIM / 32, dim3(32, 8)>>>(w2);
    // 2) s = row-sums of scaled weight2
    k_rowsum_s<<<DDIM, 256>>>(w2);
    // 3) xs[b]
    k_norm_dot<<<B, 256>>>(x, p_xs);
    // 4) ms[c]  (256 MB read — the big one besides the output)
    k_norm_dot<<<C, 256>>>(w, p_ms);
    // 5) logit stream-out (512 MB write)
    dim3 grid5(C / (4 * 256 * 8), B);
    k_logit<<<grid5, 256>>>(out, C);
}